// round 4
// baseline (speedup 1.0000x reference)
#include <cuda_runtime.h>
#include <cstdint>

// ---------------------------------------------------------------------------
// Problem: u [2,64,128,128] f32, w_phi [64,64] f32.
// phi[b,o,y,x] = sum_i w[o,i] * u[b,i,y,x]
// e(x) = 3x3 patch (pad 1) of phi  -> 576-dim
// scores[x,o] = [x+o in bounds] * e(x) . e(x+o),  o in 7x7 window
// out = softmax over 49, shape [2,128,128,1,49]
//
// Decomposition: C(y,o) = sum_c phi_z(y,c) phi_z(y+o,c)  (phi zero-extended)
//                scores(x,o) = mask * sum_{dp in 3x3} C(x+dp, o)
// ---------------------------------------------------------------------------

#define H 128
#define WD 128
#define CCH 64
#define PADP 4          // window(3) + patch(1)
#define HP (H + 2*PADP) // 136
#define NPIX (2 * HP * HP)

// zero-padded phi scratch: [b][yy][xx][c], c contiguous
__device__ float g_phi[2 * HP * HP * CCH];

// ===========================================================================
// Kernel 1: phi = W @ u per pixel, written zero-padded, channel-contiguous.
// ===========================================================================
__global__ void __launch_bounds__(128) phi_kernel(const float* __restrict__ u,
                                                  const float* __restrict__ w) {
    __shared__ float sW[CCH * CCH];
    for (int i = threadIdx.x; i < CCH * CCH; i += blockDim.x) sW[i] = w[i];
    __syncthreads();

    int gid = blockIdx.x * blockDim.x + threadIdx.x;
    if (gid >= NPIX) return;
    int b   = gid / (HP * HP);
    int rem = gid % (HP * HP);
    int yy  = rem / HP, xx = rem % HP;
    int y = yy - PADP, x = xx - PADP;

    float4* outp = reinterpret_cast<float4*>(g_phi) + (size_t)gid * (CCH / 4);

    if ((unsigned)y >= (unsigned)H || (unsigned)x >= (unsigned)WD) {
        float4 z = make_float4(0.f, 0.f, 0.f, 0.f);
        #pragma unroll
        for (int k = 0; k < CCH / 4; k++) outp[k] = z;
        return;
    }

    const float* up = u + ((size_t)b * CCH) * (H * WD) + y * WD + x;
    float acc[CCH];
    #pragma unroll
    for (int o = 0; o < CCH; o++) acc[o] = 0.f;

    const float4* sW4 = reinterpret_cast<const float4*>(sW);
    for (int i4 = 0; i4 < CCH / 4; i4++) {
        float u0 = up[(4 * i4 + 0) * (H * WD)];
        float u1 = up[(4 * i4 + 1) * (H * WD)];
        float u2 = up[(4 * i4 + 2) * (H * WD)];
        float u3 = up[(4 * i4 + 3) * (H * WD)];
        #pragma unroll
        for (int o = 0; o < CCH; o++) {
            float4 wv = sW4[o * (CCH / 4) + i4];  // smem broadcast
            acc[o] = fmaf(wv.x, u0, fmaf(wv.y, u1, fmaf(wv.z, u2, fmaf(wv.w, u3, acc[o]))));
        }
    }
    #pragma unroll
    for (int k = 0; k < CCH / 4; k++)
        outp[k] = make_float4(acc[4 * k], acc[4 * k + 1], acc[4 * k + 2], acc[4 * k + 3]);
}

// ===========================================================================
// Kernel 2: fused C-maps + 3x3 box-sum + mask + softmax.
// Tile 16x16 outputs per block. phi halo region 24x24, C region 18x18 x 49.
// ===========================================================================
#define TILE 16
#define REGN 24           // 24x24 phi positions
#define CPOS 18           // 18x18 C positions
#define CHUNK 32          // channels per smem pass
#define PHI_STRIDE 36     // floats per position (36 mod 32 == 4 -> conflict-free LDS.128)
#define S_PHI_FLOATS (REGN * REGN * PHI_STRIDE)   // 20736
#define S_C_FLOATS   (CPOS * CPOS * 49)           // 15876 (stride 49 odd -> conflict-free)
#define SMEM_BYTES   ((S_PHI_FLOATS + S_C_FLOATS) * 4)  // 146448

__global__ void __launch_bounds__(256) att_kernel(float* __restrict__ out) {
    extern __shared__ float smem[];
    float*  s_phi  = smem;
    float4* s_phi4 = reinterpret_cast<float4*>(s_phi);
    float*  C_s    = smem + S_PHI_FLOATS;

    int tid = threadIdx.x;
    int b   = blockIdx.z;
    int ty0 = blockIdx.y * TILE;
    int tx0 = blockIdx.x * TILE;

    const float4* gp4 = reinterpret_cast<const float4*>(g_phi);

    for (int ch = 0; ch < CCH / CHUNK; ch++) {
        // ---- cooperative load of 24x24 x CHUNK phi region ----
        for (int idx = tid; idx < REGN * REGN * (CHUNK / 4); idx += 256) {
            int pos = idx >> 3;       // CHUNK/4 == 8
            int q   = idx & 7;
            int gy  = ty0 + pos / REGN;   // padded coords (tile origin maps to padded origin)
            int gx  = tx0 + pos % REGN;
            float4 v = gp4[(((size_t)b * HP + gy) * HP + gx) * (CCH / 4) + ch * (CHUNK / 4) + q];
            s_phi4[pos * (PHI_STRIDE / 4) + q] = v;
        }
        __syncthreads();

        // ---- C(y,o) accumulation: thread owns C positions yl, yl+256 ----
        for (int yl = tid; yl < CPOS * CPOS; yl += 256) {
            int cy = yl / CPOS, cx = yl % CPOS;
            const float4* pb = s_phi4 + ((cy + 3) * REGN + (cx + 3)) * (PHI_STRIDE / 4);
            float4 py[CHUNK / 4];
            #pragma unroll
            for (int k = 0; k < CHUNK / 4; k++) py[k] = pb[k];

            float* crow = C_s + yl * 49;
            for (int oy = -3; oy <= 3; oy++) {
                #pragma unroll
                for (int ox = -3; ox <= 3; ox++) {
                    const float4* q = pb + (oy * REGN + ox) * (PHI_STRIDE / 4);
                    float acc = 0.f;
                    #pragma unroll
                    for (int k = 0; k < CHUNK / 4; k++) {
                        float4 qv = q[k];
                        acc = fmaf(py[k].x, qv.x, acc);
                        acc = fmaf(py[k].y, qv.y, acc);
                        acc = fmaf(py[k].z, qv.z, acc);
                        acc = fmaf(py[k].w, qv.w, acc);
                    }
                    int o = (oy + 3) * 7 + (ox + 3);
                    if (ch == 0) crow[o] = acc;
                    else         crow[o] += acc;
                }
            }
        }
        __syncthreads();
    }

    // ---- per-pixel 3x3 box-sum + boundary mask + softmax ----
    int r  = tid >> 4, s = tid & 15;
    int gy = ty0 + r,  gx = tx0 + s;

    float sc[49];
    float m = -1e30f;
    #pragma unroll
    for (int o = 0; o < 49; o++) {
        int oy = o / 7 - 3, ox = o % 7 - 3;
        float v = 0.f;
        if ((unsigned)(gy + oy) < (unsigned)H && (unsigned)(gx + ox) < (unsigned)WD) {
            #pragma unroll
            for (int dy = 0; dy < 3; dy++)
                #pragma unroll
                for (int dx = 0; dx < 3; dx++)
                    v += C_s[((r + dy) * CPOS + (s + dx)) * 49 + o];
        }
        sc[o] = v;
        m = fmaxf(m, v);
    }
    float sum = 0.f;
    #pragma unroll
    for (int o = 0; o < 49; o++) {
        float e = __expf(sc[o] - m);
        sc[o] = e;
        sum += e;
    }
    float inv = 1.0f / sum;
    float* op = out + (((size_t)b * H + gy) * WD + gx) * 49;
    #pragma unroll
    for (int o = 0; o < 49; o++) op[o] = sc[o] * inv;
}

// ===========================================================================
extern "C" void kernel_launch(void* const* d_in, const int* in_sizes, int n_in,
                              void* d_out, int out_size) {
    (void)in_sizes; (void)n_in; (void)out_size;
    const float* u = (const float*)d_in[0];
    const float* w = (const float*)d_in[1];
    float* out = (float*)d_out;

    phi_kernel<<<(NPIX + 127) / 128, 128>>>(u, w);

    cudaFuncSetAttribute(att_kernel, cudaFuncAttributeMaxDynamicSharedMemorySize, SMEM_BYTES);
    att_kernel<<<dim3(WD / TILE, H / TILE, 2), 256, SMEM_BYTES>>>(out);
}

// round 6
// speedup vs baseline: 1.2432x; 1.2432x over previous
#include <cuda_runtime.h>
#include <cstdint>

// ---------------------------------------------------------------------------
// u [2,64,128,128] f32, w_phi [64,64] f32.
// phi = 1x1 conv; e = 3x3 unfold(phi); scores(x,o) = mask * e(x).e(x+o), o in 7x7
// out = softmax_49, [2,128,128,1,49]
// Decomposition: C(y,o) = sum_c phi_z(y,c) phi_z(y+o,c)
//                scores(x,o) = mask(x+o) * sum_{dp in 3x3} C(x+dp,o)
// ---------------------------------------------------------------------------

#define H 128
#define WD 128
#define CCH 64
#define HWSZ (H * WD)
#define PADP 4
#define HP (H + 2 * PADP)     // 136
#define NPIX (2 * HP * HP)
#define NPAIR (NPIX / 2)      // 18496

// zero-padded phi scratch: [b][yy][xx][c], c contiguous
__device__ float g_phi[2 * HP * HP * CCH];

// ===========================================================================
// Kernel 1: phi = W @ u, 2 adjacent-x pixels per thread (validity identical),
// W in smem (warp-uniform broadcast amortized over 2 pixels = 2 B/FMA).
// ===========================================================================
__global__ void __launch_bounds__(128) phi_kernel(const float* __restrict__ u,
                                                  const float* __restrict__ w) {
    __shared__ float sW[CCH * CCH];
    for (int i = threadIdx.x; i < CCH * CCH; i += 128) sW[i] = w[i];
    __syncthreads();

    int gid = blockIdx.x * 128 + threadIdx.x;
    if (gid >= NPAIR) return;
    int b    = gid / (HP * HP / 2);
    int rem  = gid % (HP * HP / 2);
    int yy   = rem / (HP / 2);
    int xx2  = (rem % (HP / 2)) * 2;        // even padded x
    int y = yy - PADP, x0 = xx2 - PADP;     // x0 even

    float4* o0 = reinterpret_cast<float4*>(g_phi)
               + ((size_t)b * HP * HP + (size_t)yy * HP + xx2) * (CCH / 4);
    float4* o1 = o0 + (CCH / 4);

    // x0 even => x0 valid implies x0+1 valid; y invalid kills both.
    bool valid = ((unsigned)y < (unsigned)H) && ((unsigned)x0 < (unsigned)WD);
    if (!valid) {
        float4 z = make_float4(0.f, 0.f, 0.f, 0.f);
        #pragma unroll
        for (int k = 0; k < CCH / 4; k++) { o0[k] = z; o1[k] = z; }
        return;
    }

    const float* up = u + (size_t)b * CCH * HWSZ + y * WD + x0;
    const float4* sW4 = reinterpret_cast<const float4*>(sW);

    float acc0[CCH], acc1[CCH];
    #pragma unroll
    for (int o = 0; o < CCH; o++) { acc0[o] = 0.f; acc1[o] = 0.f; }

    // software-pipelined u loads (float2 covers both pixels)
    float2 cur[4];
    #pragma unroll
    for (int c = 0; c < 4; c++)
        cur[c] = *reinterpret_cast<const float2*>(up + c * HWSZ);

    #pragma unroll 1
    for (int i4 = 0; i4 < CCH / 4; i4++) {
        float2 nxt[4];
        if (i4 < CCH / 4 - 1) {
            #pragma unroll
            for (int c = 0; c < 4; c++)
                nxt[c] = *reinterpret_cast<const float2*>(up + ((i4 + 1) * 4 + c) * HWSZ);
        }
        #pragma unroll
        for (int o = 0; o < CCH; o++) {
            float4 wv = sW4[o * (CCH / 4) + i4];   // uniform broadcast
            acc0[o] = fmaf(wv.x, cur[0].x, fmaf(wv.y, cur[1].x,
                      fmaf(wv.z, cur[2].x, fmaf(wv.w, cur[3].x, acc0[o]))));
            acc1[o] = fmaf(wv.x, cur[0].y, fmaf(wv.y, cur[1].y,
                      fmaf(wv.z, cur[2].y, fmaf(wv.w, cur[3].y, acc1[o]))));
        }
        #pragma unroll
        for (int c = 0; c < 4; c++) cur[c] = nxt[c];
    }

    #pragma unroll
    for (int k = 0; k < CCH / 4; k++) {
        o0[k] = make_float4(acc0[4 * k], acc0[4 * k + 1], acc0[4 * k + 2], acc0[4 * k + 3]);
        o1[k] = make_float4(acc1[4 * k], acc1[4 * k + 1], acc1[4 * k + 2], acc1[4 * k + 3]);
    }
}

// ===========================================================================
// Kernel 2: fused C-maps (single 64-ch pass) + 3x3 box-sum + mask + softmax.
// 16x16 output tile, 384 threads. phi halo 24x24 (stride 68 floats -> 68%32=4,
// conflict-free LDS.128), C region 18x18 x 49 (stride 49 odd, conflict-free).
// ===========================================================================
#define TILE 16
#define REGN 24
#define CPOS 18
#define PHI_V4 17                                  // float4 per position (16 data + 1 pad)
#define S_PHI_FLOATS (REGN * REGN * PHI_V4 * 4)    // 39168
#define S_C_FLOATS   (CPOS * CPOS * 49)            // 15876
#define SMEM_BYTES   ((S_PHI_FLOATS + S_C_FLOATS) * 4)  // 220176

__global__ void __launch_bounds__(384) att_kernel(float* __restrict__ out) {
    extern __shared__ float smem[];
    float4* s_phi4 = reinterpret_cast<float4*>(smem);
    float*  C_s    = smem + S_PHI_FLOATS;

    int tid = threadIdx.x;
    int b   = blockIdx.z;
    int ty0 = blockIdx.y * TILE;
    int tx0 = blockIdx.x * TILE;

    const float4* gp4 = reinterpret_cast<const float4*>(g_phi);

    // ---- load 24x24 x 64ch phi halo (tile origin maps to padded origin) ----
    for (int idx = tid; idx < REGN * REGN * (CCH / 4); idx += 384) {
        int pos = idx >> 4;            // CCH/4 == 16
        int q   = idx & 15;
        int gy  = ty0 + pos / REGN;
        int gx  = tx0 + pos % REGN;
        s_phi4[pos * PHI_V4 + q] =
            gp4[(((size_t)b * HP + gy) * HP + gx) * (CCH / 4) + q];
    }
    __syncthreads();

    // ---- C(y,o): one position per thread, py register-cached, 8 partials ----
    if (tid < CPOS * CPOS) {
        int cy = tid / CPOS, cx = tid % CPOS;
        const float4* pb = s_phi4 + ((cy + 3) * REGN + (cx + 3)) * PHI_V4;

        float4 py[16];
        #pragma unroll
        for (int k = 0; k < 16; k++) py[k] = pb[k];

        float* crow = C_s + tid * 49;
        for (int oy = -3; oy <= 3; oy++) {
            #pragma unroll
            for (int ox = -3; ox <= 3; ox++) {
                const float4* qb = pb + (oy * REGN + ox) * PHI_V4;
                float a0 = 0.f, a1 = 0.f, a2 = 0.f, a3 = 0.f;
                float a4 = 0.f, a5 = 0.f, a6 = 0.f, a7 = 0.f;
                #pragma unroll
                for (int k = 0; k < 16; k += 2) {
                    float4 q0 = qb[k], q1 = qb[k + 1];
                    a0 = fmaf(py[k].x,     q0.x, a0);
                    a1 = fmaf(py[k].y,     q0.y, a1);
                    a2 = fmaf(py[k].z,     q0.z, a2);
                    a3 = fmaf(py[k].w,     q0.w, a3);
                    a4 = fmaf(py[k + 1].x, q1.x, a4);
                    a5 = fmaf(py[k + 1].y, q1.y, a5);
                    a6 = fmaf(py[k + 1].z, q1.z, a6);
                    a7 = fmaf(py[k + 1].w, q1.w, a7);
                }
                crow[(oy + 3) * 7 + (ox + 3)] =
                    ((a0 + a1) + (a2 + a3)) + ((a4 + a5) + (a6 + a7));
            }
        }
    }
    __syncthreads();

    // ---- per-pixel 3x3 box-sum + boundary mask + softmax ----
    if (tid < TILE * TILE) {
        int r  = tid >> 4, s = tid & 15;
        int gy = ty0 + r,  gx = tx0 + s;

        float sc[49];
        float m = -1e30f;
        #pragma unroll
        for (int o = 0; o < 49; o++) {
            int oy = o / 7 - 3, ox = o % 7 - 3;
            float v = 0.f;
            if ((unsigned)(gy + oy) < (unsigned)H && (unsigned)(gx + ox) < (unsigned)WD) {
                #pragma unroll
                for (int dy = 0; dy < 3; dy++)
                    #pragma unroll
                    for (int dx = 0; dx < 3; dx++)
                        v += C_s[((r + dy) * CPOS + (s + dx)) * 49 + o];
            }
            sc[o] = v;
            m = fmaxf(m, v);
        }
        float sum = 0.f;
        #pragma unroll
        for (int o = 0; o < 49; o++) {
            float e = __expf(sc[o] - m);
            sc[o] = e;
            sum += e;
        }
        float inv = 1.0f / sum;
        float* op = out + (((size_t)b * H + gy) * WD + gx) * 49;
        #pragma unroll
        for (int o = 0; o < 49; o++) op[o] = sc[o] * inv;
    }
}

// ===========================================================================
extern "C" void kernel_launch(void* const* d_in, const int* in_sizes, int n_in,
                              void* d_out, int out_size) {
    (void)in_sizes; (void)n_in; (void)out_size;
    const float* u = (const float*)d_in[0];
    const float* w = (const float*)d_in[1];
    float* out = (float*)d_out;

    phi_kernel<<<(NPAIR + 127) / 128, 128>>>(u, w);

    cudaFuncSetAttribute(att_kernel, cudaFuncAttributeMaxDynamicSharedMemorySize, SMEM_BYTES);
    att_kernel<<<dim3(WD / TILE, H / TILE, 2), 384, SMEM_BYTES>>>(out);
}